// round 4
// baseline (speedup 1.0000x reference)
#include <cuda_runtime.h>
#include <math.h>

#define BATCH 8
#define DOUT  16

// ---------------------------------------------------------------------------
// Scratch (device globals -- no allocation allowed)
// ---------------------------------------------------------------------------
__device__ float g_pred[(size_t)BATCH * 596 * 100 * DOUT];   // max: level 2, 30.5 MB
__device__ float g_S[2 * BATCH * 100 * DOUT];                // [S | S2], max C=100
__device__ float g_vint[BATCH * 100 * DOUT];                 // iter-0 v

// ---------------------------------------------------------------------------
__global__ void zero_kernel(int n) {
    int i = blockIdx.x * blockDim.x + threadIdx.x;
    if (i < n) g_S[i] = 0.f;
}

// ---------------------------------------------------------------------------
// pred[b,i,c,d] = sum_k W[i,c,d,k] * Xlvl[b,i,k]
// also accumulates S[b,c,d] += sum_i pred  (register acc + 1 atomic/thread/b)
// Xlvl: i < skip  -> X[b*9216 + i*K + k]   (works for both [8,1152,8] and the
//                    [8,576,16] reshape: per-b block is 9216 floats either way)
//       i >= skip -> Vprev[(b*cprev + (i-skip))*16 + k]
// ---------------------------------------------------------------------------
template<int N, int C, int K, int IPAR, int ILOOP, int CTILE>
__global__ void pred_kernel(const float* __restrict__ X,
                            const float* __restrict__ W,
                            const float* __restrict__ Vprev,
                            int skip, int cprev)
{
    constexpr int ICHUNK = IPAR * ILOOP;
    constexpr int TPB    = IPAR * CTILE * DOUT;
    __shared__ float Xs[ICHUNK][BATCH][K];

    const int tid = threadIdx.x;
    const int i0  = blockIdx.x * ICHUNK;

    // cooperative load of input capsule vectors for this i-chunk
    for (int idx = tid; idx < ICHUNK * BATCH * K; idx += TPB) {
        int il = idx / (BATCH * K);
        int r  = idx % (BATCH * K);
        int b  = r / K, k = r % K;
        int gi = i0 + il;
        float v;
        if (gi < skip) v = X[b * 9216 + gi * K + k];
        else           v = Vprev[(b * cprev + (gi - skip)) * DOUT + k];
        Xs[il][b][k] = v;
    }
    __syncthreads();

    const int isub = tid / (CTILE * DOUT);
    const int rem  = tid % (CTILE * DOUT);
    const int c    = blockIdx.y * CTILE + rem / DOUT;
    const int d    = rem % DOUT;

    float acc[BATCH];
#pragma unroll
    for (int b = 0; b < BATCH; b++) acc[b] = 0.f;

#pragma unroll
    for (int il2 = 0; il2 < ILOOP; ++il2) {
        const int iloc = isub * ILOOP + il2;
        const int i    = i0 + iloc;
        const float* wp = W + ((size_t)(i * C + c) * DOUT + d) * K;
        float w[K];
#pragma unroll
        for (int k4 = 0; k4 < K / 4; k4++) {
            float4 t = reinterpret_cast<const float4*>(wp)[k4];
            w[4*k4+0] = t.x; w[4*k4+1] = t.y; w[4*k4+2] = t.z; w[4*k4+3] = t.w;
        }
#pragma unroll
        for (int b = 0; b < BATCH; b++) {
            float p = 0.f;
#pragma unroll
            for (int k = 0; k < K; k++) p += w[k] * Xs[iloc][b][k];
            acc[b] += p;
            g_pred[(((size_t)b * N + i) * C + c) * DOUT + d] = p;
        }
    }
#pragma unroll
    for (int b = 0; b < BATCH; b++)
        atomicAdd(&g_S[(b * C + c) * DOUT + d], acc[b]);
}

// ---------------------------------------------------------------------------
// squash: v = (sq/(1+sq)) * s / sqrt(sq + 1e-7), s = S*scale
// use_s2 selects the S2 half of g_S. Vout==nullptr -> write g_vint.
// ---------------------------------------------------------------------------
__global__ void squash_kernel(int C, float scale, int use_s2, float* Vout)
{
    int t = blockIdx.x * blockDim.x + threadIdx.x;
    if (t >= BATCH * C) return;
    const float* S = g_S + (use_s2 ? BATCH * C * DOUT : 0);
    float* V = Vout ? Vout : g_vint;
    const float* s = S + t * DOUT;
    float sv[DOUT];
    float sq = 0.f;
#pragma unroll
    for (int d = 0; d < DOUT; d++) { float x = s[d] * scale; sv[d] = x; sq += x * x; }
    float f = sq / ((1.f + sq) * sqrtf(sq + 1e-7f));
    float* v = V + t * DOUT;
#pragma unroll
    for (int d = 0; d < DOUT; d++) v[d] = f * sv[d];
}

// ---------------------------------------------------------------------------
// routing iter 1: per (b,i): logits_c = sum_d pred*v_int ; c = softmax_c ;
// S2[b,c,d] += sum_i c_c * pred[b,i,c,d]
// block = (i-chunk, b); shared accumulation, one atomic per element per block
// ---------------------------------------------------------------------------
template<int N, int C, int IC>
__global__ void route_kernel()
{
    constexpr int CD = C * DOUT;
    __shared__ float vsh[CD];
    __shared__ float accs[CD];
    __shared__ float preds[CD];
    __shared__ float logit[C];
    __shared__ float inv_s;

    const int tid = threadIdx.x;
    const int b   = blockIdx.y;
    const int i0  = blockIdx.x * IC;

    for (int idx = tid; idx < CD; idx += blockDim.x) {
        vsh[idx]  = g_vint[b * CD + idx];
        accs[idx] = 0.f;
    }
    __syncthreads();

    for (int ii = 0; ii < IC; ++ii) {
        const int i = i0 + ii;
        const float4* pp =
            reinterpret_cast<const float4*>(g_pred + (size_t)(b * N + i) * CD);
        for (int idx = tid; idx < CD / 4; idx += blockDim.x)
            reinterpret_cast<float4*>(preds)[idx] = pp[idx];
        __syncthreads();

        if (tid < C) {
            float lg = 0.f;
#pragma unroll
            for (int dd = 0; dd < DOUT; dd++) {
                int d = (dd + tid) & (DOUT - 1);   // rotate to dodge bank conflicts
                lg += preds[tid * DOUT + d] * vsh[tid * DOUT + d];
            }
            logit[tid] = lg;
        }
        __syncthreads();

        if (tid < 32) {
            float m = -1e30f;
            for (int t = tid; t < C; t += 32) m = fmaxf(m, logit[t]);
#pragma unroll
            for (int o = 16; o; o >>= 1) m = fmaxf(m, __shfl_xor_sync(0xffffffffu, m, o));
            float sum = 0.f;
            for (int t = tid; t < C; t += 32) {
                float e = expf(logit[t] - m);
                logit[t] = e;
                sum += e;
            }
#pragma unroll
            for (int o = 16; o; o >>= 1) sum += __shfl_xor_sync(0xffffffffu, sum, o);
            if (tid == 0) inv_s = 1.f / sum;
        }
        __syncthreads();

        float inv = inv_s;
        for (int idx = tid; idx < CD; idx += blockDim.x)
            accs[idx] += logit[idx >> 4] * inv * preds[idx];
        __syncthreads();
    }

    float* S2 = g_S + BATCH * CD;
    for (int idx = tid; idx < CD; idx += blockDim.x)
        atomicAdd(&S2[b * CD + idx], accs[idx]);
}

// ---------------------------------------------------------------------------
extern "C" void kernel_launch(void* const* d_in, const int* in_sizes, int n_in,
                              void* d_out, int out_size)
{
    const float* X  = (const float*)d_in[0];   // [8,1152,8]
    const float* W0 = (const float*)d_in[1];   // [1152,8,16,8]
    const float* W1 = (const float*)d_in[2];   // [584,20,16,16]
    const float* W2 = (const float*)d_in[3];   // [596,100,16,16]
    float* out = (float*)d_out;
    float* v0 = out;                 // [8][8][16]
    float* v1 = out + 8 * 8 * 16;    // [8][20][16]
    float* v2 = v1 + 8 * 20 * 16;    // [8][100][16]

    // ---- level 0: X[8,1152,8] -> v0[8,8,16] ----
    {
        const int C = 8;
        int nz = 2 * BATCH * C * DOUT;
        zero_kernel<<<(nz + 255) / 256, 256>>>(nz);
        pred_kernel<1152, 8, 8, 4, 2, 8><<<dim3(144, 1), 512>>>(X, W0, X, 1152, 1);
        squash_kernel<<<1, 128>>>(C, 1.f / C, 0, nullptr);
        route_kernel<1152, 8, 8><<<dim3(144, 8), 128>>>();
        squash_kernel<<<1, 128>>>(C, 1.f, 1, v0);
    }

    // ---- level 1: concat(p[8,576,16], v0) -> v1[8,20,16] ----
    {
        const int C = 20;
        int nz = 2 * BATCH * C * DOUT;
        zero_kernel<<<(nz + 255) / 256, 256>>>(nz);
        pred_kernel<584, 20, 16, 2, 2, 20><<<dim3(146, 1), 640>>>(X, W1, v0, 576, 8);
        squash_kernel<<<(BATCH * C + 127) / 128, 128>>>(C, 1.f / C, 0, nullptr);
        route_kernel<584, 20, 4><<<dim3(146, 8), 256>>>();
        squash_kernel<<<(BATCH * C + 127) / 128, 128>>>(C, 1.f, 1, v1);
    }

    // ---- level 2: concat(p[8,576,16], v1) -> v2[8,100,16] ----
    {
        const int C = 100;
        int nz = 2 * BATCH * C * DOUT;
        zero_kernel<<<(nz + 255) / 256, 256>>>(nz);
        pred_kernel<596, 100, 16, 1, 4, 50><<<dim3(149, 2), 800>>>(X, W2, v1, 576, 20);
        squash_kernel<<<(BATCH * C + 127) / 128, 128>>>(C, 1.f / C, 0, nullptr);
        route_kernel<596, 100, 4><<<dim3(149, 8), 256>>>();
        squash_kernel<<<(BATCH * C + 127) / 128, 128>>>(C, 1.f, 1, v2);
    }
}

// round 6
// speedup vs baseline: 1.3641x; 1.3641x over previous
#include <cuda_runtime.h>
#include <math.h>

#define BATCH 8
#define DOUT  16

// ---------------------------------------------------------------------------
// Scratch (device globals -- no allocation allowed)
// ---------------------------------------------------------------------------
__device__ float g_pred[(size_t)BATCH * 596 * 100 * DOUT];   // max: level 2, 30.5 MB
// S regions (S | S2) per level, disjoint:
//   L0: [0,2048)   L1: [2048,7168)   L2: [7168,32768)
__device__ float g_S[32768];
__device__ unsigned g_ctr[4];   // zero-initialized; each use self-resets

#define SOFF0 0
#define SOFF1 2048
#define SOFF2 7168

// ---------------------------------------------------------------------------
__global__ void zero_kernel() {
    int i = blockIdx.x * 256 + threadIdx.x;
    if (i < 32768) g_S[i] = 0.f;
}

// ---------------------------------------------------------------------------
// squash of one 16-dim capsule: out = (sq/(1+sq)) * s / sqrt(sq+eps), s = in*scale
// ---------------------------------------------------------------------------
__device__ __forceinline__ void squash16(const float* __restrict__ s, float scale,
                                         float* __restrict__ out)
{
    float4 a[4];
    float sq = 0.f;
#pragma unroll
    for (int j = 0; j < 4; j++) {
        float4 t = __ldcg(reinterpret_cast<const float4*>(s) + j);
        t.x *= scale; t.y *= scale; t.z *= scale; t.w *= scale;
        sq += t.x*t.x + t.y*t.y + t.z*t.z + t.w*t.w;
        a[j] = t;
    }
    float f = sq / ((1.f + sq) * sqrtf(sq + 1e-7f));
#pragma unroll
    for (int j = 0; j < 4; j++) {
        a[j].x *= f; a[j].y *= f; a[j].z *= f; a[j].w *= f;
        reinterpret_cast<float4*>(out)[j] = a[j];
    }
}

// ---------------------------------------------------------------------------
// pred[b,i,c,d] = sum_k W[i,c,d,k] * Xlvl[b,i,k]
// also accumulates S[b,c,d] += sum_i pred  (register acc + 1 atomic/thread/b)
// ---------------------------------------------------------------------------
template<int N, int C, int K, int IPAR, int ILOOP, int CTILE>
__global__ __launch_bounds__(IPAR * CTILE * DOUT)
void pred_kernel(const float* __restrict__ X,
                 const float* __restrict__ W,
                 const float* __restrict__ Vprev,
                 int skip, int cprev, int soff)
{
    constexpr int ICHUNK = IPAR * ILOOP;
    constexpr int TPB    = IPAR * CTILE * DOUT;
    __shared__ float Xs[ICHUNK][BATCH][K];

    const int tid = threadIdx.x;
    const int i0  = blockIdx.x * ICHUNK;

    for (int idx = tid; idx < ICHUNK * BATCH * K; idx += TPB) {
        int il = idx / (BATCH * K);
        int r  = idx % (BATCH * K);
        int b  = r / K, k = r % K;
        int gi = i0 + il;
        float v;
        if (gi < skip) v = X[b * 9216 + gi * K + k];
        else           v = Vprev[(b * cprev + (gi - skip)) * DOUT + k];
        Xs[il][b][k] = v;
    }
    __syncthreads();

    const int isub = tid / (CTILE * DOUT);
    const int rem  = tid % (CTILE * DOUT);
    const int c    = blockIdx.y * CTILE + rem / DOUT;
    const int d    = rem % DOUT;

    float acc[BATCH];
#pragma unroll
    for (int b = 0; b < BATCH; b++) acc[b] = 0.f;

#pragma unroll
    for (int il2 = 0; il2 < ILOOP; ++il2) {
        const int iloc = isub * ILOOP + il2;
        const int i    = i0 + iloc;
        const float* wp = W + ((size_t)(i * C + c) * DOUT + d) * K;
        float w[K];
#pragma unroll
        for (int k4 = 0; k4 < K / 4; k4++) {
            float4 t = reinterpret_cast<const float4*>(wp)[k4];
            w[4*k4+0] = t.x; w[4*k4+1] = t.y; w[4*k4+2] = t.z; w[4*k4+3] = t.w;
        }
#pragma unroll
        for (int b = 0; b < BATCH; b++) {
            float p = 0.f;
#pragma unroll
            for (int k = 0; k < K; k++) p += w[k] * Xs[iloc][b][k];
            acc[b] += p;
            g_pred[(((size_t)b * N + i) * C + c) * DOUT + d] = p;
        }
    }
#pragma unroll
    for (int b = 0; b < BATCH; b++)
        atomicAdd(&g_S[soff + (b * C + c) * DOUT + d], acc[b]);
}

// ---------------------------------------------------------------------------
// route level 0: C=8, CD=128, N=1152.  grid (19, 8), block 256.
// warp-per-i-stride; lane holds 4 (c,d) elems; no inner syncs.
// Butterfly over xor {4,8,16} spans 8 lanes = one lane per capsule group,
// so the reduced sum is exactly sum_c e_c (weight = e/s, NO extra factor).
// ---------------------------------------------------------------------------
__global__ __launch_bounds__(256) void route0_kernel(float* __restrict__ v0)
{
    __shared__ float vsh[128];
    __shared__ unsigned s_done;
    const int tid = threadIdx.x, lane = tid & 31, warp = tid >> 5;
    const int b = blockIdx.y;

    if (tid < 8)
        squash16(&g_S[SOFF0 + b * 128 + tid * 16], 0.125f, &vsh[tid * 16]);
    __syncthreads();

    const float4 v4 = *reinterpret_cast<const float4*>(&vsh[lane * 4]);
    float ax = 0.f, ay = 0.f, az = 0.f, aw = 0.f;
    const int wg = blockIdx.x * 8 + warp;           // 0..151 per b

    for (int i = wg; i < 1152; i += 152) {
        float4 p = *reinterpret_cast<const float4*>(
            g_pred + ((size_t)(b * 1152 + i)) * 128 + lane * 4);
        float lg = p.x*v4.x + p.y*v4.y + p.z*v4.z + p.w*v4.w;
        lg += __shfl_xor_sync(~0u, lg, 1);
        lg += __shfl_xor_sync(~0u, lg, 2);          // logit for c = lane/4
        float m = lg;
        m = fmaxf(m, __shfl_xor_sync(~0u, m, 4));
        m = fmaxf(m, __shfl_xor_sync(~0u, m, 8));
        m = fmaxf(m, __shfl_xor_sync(~0u, m, 16));
        float e = __expf(lg - m);
        float s = e;
        s += __shfl_xor_sync(~0u, s, 4);
        s += __shfl_xor_sync(~0u, s, 8);
        s += __shfl_xor_sync(~0u, s, 16);           // = sum_c e_c (once each)
        float w = e / s;
        ax += w * p.x; ay += w * p.y; az += w * p.z; aw += w * p.w;
    }
    float* S2 = &g_S[SOFF0 + 1024 + b * 128 + lane * 4];
    atomicAdd(S2 + 0, ax); atomicAdd(S2 + 1, ay);
    atomicAdd(S2 + 2, az); atomicAdd(S2 + 3, aw);

    __threadfence();
    __syncthreads();
    if (tid == 0) s_done = atomicAdd(&g_ctr[0], 1u);
    __syncthreads();
    if (s_done == 151u) {                            // last of 152 blocks
        __threadfence();
        if (tid < 64)
            squash16(&g_S[SOFF0 + 1024 + tid * 16], 1.f, v0 + tid * 16);
        if (tid == 0) g_ctr[0] = 0u;
    }
}

// ---------------------------------------------------------------------------
// route level 1: C=20, CD=320, N=584.  grid (20, 8), block 256.
// lane layout: element 32*cc + lane  (c = 2*cc + lane/16, d = lane%16)
// ---------------------------------------------------------------------------
__global__ __launch_bounds__(256) void route1_kernel(float* __restrict__ v1)
{
    __shared__ float vsh[320];
    __shared__ unsigned s_done;
    const int tid = threadIdx.x, lane = tid & 31, warp = tid >> 5;
    const int b = blockIdx.y;

    if (tid < 20)
        squash16(&g_S[SOFF1 + b * 320 + tid * 16], 1.f / 20.f, &vsh[tid * 16]);
    __syncthreads();

    float v[10], acc[10];
#pragma unroll
    for (int cc = 0; cc < 10; cc++) { v[cc] = vsh[32 * cc + lane]; acc[cc] = 0.f; }

    const int wg = blockIdx.x * 8 + warp;           // 0..159 per b
    for (int i = wg; i < 584; i += 160) {
        const float* pb = g_pred + ((size_t)(b * 584 + i)) * 320;
        float p[10], lg[10];
#pragma unroll
        for (int cc = 0; cc < 10; cc++) {
            p[cc] = pb[32 * cc + lane];
            float t = p[cc] * v[cc];
            t += __shfl_xor_sync(~0u, t, 1);
            t += __shfl_xor_sync(~0u, t, 2);
            t += __shfl_xor_sync(~0u, t, 4);
            t += __shfl_xor_sync(~0u, t, 8);
            lg[cc] = t;
        }
        float m = lg[0];
#pragma unroll
        for (int cc = 1; cc < 10; cc++) m = fmaxf(m, lg[cc]);
        m = fmaxf(m, __shfl_xor_sync(~0u, m, 16));
        float tot = 0.f;
#pragma unroll
        for (int cc = 0; cc < 10; cc++) { lg[cc] = __expf(lg[cc] - m); tot += lg[cc]; }
        tot += __shfl_xor_sync(~0u, tot, 16);
        float inv = 1.f / tot;
#pragma unroll
        for (int cc = 0; cc < 10; cc++) acc[cc] += lg[cc] * inv * p[cc];
    }
#pragma unroll
    for (int cc = 0; cc < 10; cc++)
        atomicAdd(&g_S[SOFF1 + 2560 + b * 320 + 32 * cc + lane], acc[cc]);

    __threadfence();
    __syncthreads();
    if (tid == 0) s_done = atomicAdd(&g_ctr[1], 1u);
    __syncthreads();
    if (s_done == 159u) {
        __threadfence();
        if (tid < 160)
            squash16(&g_S[SOFF1 + 2560 + tid * 16], 1.f, v1 + tid * 16);
        if (tid == 0) g_ctr[1] = 0u;
    }
}

// ---------------------------------------------------------------------------
// route level 2: C=100, CD=1600, N=596.  grid (38, 8), block 128 (4 warps).
// pred row kept in registers; per-warp smem accumulator; logits staged via
// per-warp smem so exps are computed ~3/lane instead of 50/lane.
// ---------------------------------------------------------------------------
__global__ __launch_bounds__(128) void route2_kernel(float* __restrict__ v2)
{
    __shared__ float vsh[1600];
    __shared__ float sacc[4][1600];
    __shared__ float slog[4][100];
    __shared__ unsigned s_done;
    const int tid = threadIdx.x, lane = tid & 31, warp = tid >> 5;
    const int b = blockIdx.y;
    const int half = lane >> 4;

    if (tid < 100)
        squash16(&g_S[SOFF2 + b * 1600 + tid * 16], 0.01f, &vsh[tid * 16]);
    for (int e = tid; e < 4 * 1600; e += 128) (&sacc[0][0])[e] = 0.f;
    __syncthreads();

    float* sa = sacc[warp];
    float* sl = slog[warp];
    const int wg = blockIdx.x * 4 + warp;           // 0..151 per b

    for (int i = wg; i < 596; i += 152) {
        const float* pb = g_pred + ((size_t)(b * 596 + i)) * 1600;
        float p[50], lg[50];
#pragma unroll
        for (int cc = 0; cc < 50; cc++) {
            p[cc] = pb[32 * cc + lane];
            float t = p[cc] * vsh[32 * cc + lane];
            t += __shfl_xor_sync(~0u, t, 1);
            t += __shfl_xor_sync(~0u, t, 2);
            t += __shfl_xor_sync(~0u, t, 4);
            t += __shfl_xor_sync(~0u, t, 8);
            lg[cc] = t;                              // logit for c = 2*cc+half
        }
        __syncwarp();
        if ((lane & 15) == 0) {
#pragma unroll
            for (int cc = 0; cc < 50; cc++) sl[2 * cc + half] = lg[cc];
        }
        __syncwarp();
        // distributed softmax over 100 logits: lane handles c = lane,+32,+64(,+96)
        float l0 = sl[lane], l1 = sl[lane + 32], l2 = sl[lane + 64];
        float l3 = (lane < 4) ? sl[lane + 96] : -1e30f;
        float m = fmaxf(fmaxf(l0, l1), fmaxf(l2, l3));
#pragma unroll
        for (int o = 16; o; o >>= 1) m = fmaxf(m, __shfl_xor_sync(~0u, m, o));
        float e0 = __expf(l0 - m), e1 = __expf(l1 - m), e2 = __expf(l2 - m);
        float e3 = (lane < 4) ? __expf(l3 - m) : 0.f;
        float tot = e0 + e1 + e2 + e3;
#pragma unroll
        for (int o = 16; o; o >>= 1) tot += __shfl_xor_sync(~0u, tot, o);
        sl[lane] = e0; sl[lane + 32] = e1; sl[lane + 64] = e2;
        if (lane < 4) sl[lane + 96] = e3;
        __syncwarp();
        float inv = 1.f / tot;
#pragma unroll
        for (int cc = 0; cc < 50; cc++) {
            float w = sl[2 * cc + half] * inv;       // broadcast LDS
            sa[32 * cc + lane] += w * p[cc];
        }
    }
    __syncthreads();
    for (int e = tid; e < 1600; e += 128) {
        float s = sacc[0][e] + sacc[1][e] + sacc[2][e] + sacc[3][e];
        atomicAdd(&g_S[SOFF2 + 12800 + b * 1600 + e], s);
    }

    __threadfence();
    __syncthreads();
    if (tid == 0) s_done = atomicAdd(&g_ctr[2], 1u);
    __syncthreads();
    if (s_done == 303u) {                            // last of 304 blocks
        __threadfence();
        for (int cap = tid; cap < 800; cap += 128)
            squash16(&g_S[SOFF2 + 12800 + cap * 16], 1.f, v2 + cap * 16);
        if (tid == 0) g_ctr[2] = 0u;
    }
}

// ---------------------------------------------------------------------------
extern "C" void kernel_launch(void* const* d_in, const int* in_sizes, int n_in,
                              void* d_out, int out_size)
{
    const float* X  = (const float*)d_in[0];   // [8,1152,8]
    const float* W0 = (const float*)d_in[1];   // [1152,8,16,8]
    const float* W1 = (const float*)d_in[2];   // [584,20,16,16]
    const float* W2 = (const float*)d_in[3];   // [596,100,16,16]
    float* out = (float*)d_out;
    float* v0 = out;                 // [8][8][16]
    float* v1 = out + 1024;          // [8][20][16]
    float* v2 = v1 + 2560;           // [8][100][16]

    zero_kernel<<<128, 256>>>();

    // ---- level 0 ----
    pred_kernel<1152, 8, 8, 4, 2, 8><<<dim3(144, 1), 512>>>(X, W0, X, 1152, 1, SOFF0);
    route0_kernel<<<dim3(19, 8), 256>>>(v0);

    // ---- level 1 ----
    pred_kernel<584, 20, 16, 2, 2, 20><<<dim3(146, 1), 640>>>(X, W1, v0, 576, 8, SOFF1);
    route1_kernel<<<dim3(20, 8), 256>>>(v1);

    // ---- level 2 ----
    pred_kernel<596, 100, 16, 1, 4, 20><<<dim3(149, 5), 320>>>(X, W2, v1, 576, 20, SOFF2);
    route2_kernel<<<dim3(38, 8), 128>>>(v2);
}